// round 15
// baseline (speedup 1.0000x reference)
#include <cuda_runtime.h>
#include <cstdint>

#define BATCH 4096
#define DIM   768
#define NEXP  16
#define KD    1536
#define KSEL  50
#define NPAIR (BATCH*2)

// ---------------- f32x2 packed-math macros (decode) ----------------
#define FMA2(d,a,b) asm("fma.rn.f32x2 %0, %1, %2, %3;" : "=l"(d) : "l"(a), "l"(b), "l"(d))
#define PACK2(d,lo,hi) asm("mov.b64 %0, {%1, %2};" : "=l"(d) : "f"(lo), "f"(hi))
#define UNPACK2(lo,hi,v) asm("mov.b64 {%0, %1}, %2;" : "=f"(lo), "=f"(hi) : "l"(v))
typedef unsigned long long u64;

// ---------------- device scratch ----------------
__device__ float g_X[BATCH * DIM];      // x - b_dec, 12.6 MB
__device__ float g_F[NPAIR * KD];       // masked relu activations, 50.3 MB
__device__ float g_w[NPAIR];
__device__ int   g_route[NPAIR];
__device__ int   g_cnt[NEXP];
__device__ int   g_list[NEXP * BATCH];
__device__ int   g_work;
__device__ int   g_done;
__device__ int   g_ntiles;
__device__ int   g_tile_e[NEXP * 32];
__device__ int   g_tile_mt[NEXP * 32];

// ---------------- tf32 helpers ----------------
__device__ __forceinline__ uint32_t f2tf(float v) {
    uint32_t r; asm("cvt.rna.tf32.f32 %0, %1;" : "=r"(r) : "f"(v)); return r;
}
__device__ __forceinline__ uint2 split_tf(float v) {
    uint2 r;
    r.x = f2tf(v);
    r.y = f2tf(v - __uint_as_float(r.x));
    return r;
}
// m16n8k8 tf32 MMA: D(4f) += A(4 b32) * B(2 b32)
__device__ __forceinline__ void mma_tf32(float* c, const uint32_t* a, const uint32_t* b) {
    asm("mma.sync.aligned.m16n8k8.row.col.f32.tf32.tf32.f32 "
        "{%0,%1,%2,%3}, {%4,%5,%6,%7}, {%8,%9}, {%0,%1,%2,%3};"
        : "+f"(c[0]), "+f"(c[1]), "+f"(c[2]), "+f"(c[3])
        : "r"(a[0]), "r"(a[1]), "r"(a[2]), "r"(a[3]), "r"(b[0]), "r"(b[1]));
}

// ---------------- init ----------------
__global__ void k_init() {
    if (threadIdx.x < NEXP) g_cnt[threadIdx.x] = 0;
    if (threadIdx.x == NEXP) g_done = 0;
}

// ---------------- gate + route + x-prep; last block builds tile table ----------------
__global__ void __launch_bounds__(128) k_gate(const float* __restrict__ x,
                                              const float* __restrict__ Wg,
                                              const float* __restrict__ bg,
                                              const float* __restrict__ b_gate,
                                              const float* __restrict__ b_dec) {
    int b = blockIdx.x * 4 + (threadIdx.x >> 5);
    int lane = threadIdx.x & 31;
    const float* xr = x + (size_t)b * DIM;

    float pe[NEXP];
#pragma unroll
    for (int e = 0; e < NEXP; e++) pe[e] = 0.f;
    for (int d = lane; d < DIM; d += 32) {
        float xv = xr[d];
        g_X[(size_t)b * DIM + d] = xv - b_dec[d];
        xv -= b_gate[d];
#pragma unroll
        for (int e = 0; e < NEXP; e++) pe[e] += xv * Wg[e * DIM + d];
    }
#pragma unroll
    for (int e = 0; e < NEXP; e++) {
#pragma unroll
        for (int o = 16; o > 0; o >>= 1) pe[e] += __shfl_xor_sync(0xffffffffu, pe[e], o);
        pe[e] += bg[e];
    }
    float m = pe[0];
#pragma unroll
    for (int e = 1; e < NEXP; e++) m = fmaxf(m, pe[e]);
    float s = 0.f;
#pragma unroll
    for (int e = 0; e < NEXP; e++) { pe[e] = expf(pe[e] - m); s += pe[e]; }
    float inv = 1.f / s;
    float v1 = -1.f, v2 = -1.f; int i1 = 0, i2 = 0;
#pragma unroll
    for (int e = 0; e < NEXP; e++) {
        float p = pe[e] * inv;
        if (p > v1)      { v2 = v1; i2 = i1; v1 = p; i1 = e; }
        else if (p > v2) { v2 = p;  i2 = e; }
    }
    float e1 = expf(v1), e2 = expf(v2);
    float w0 = e1 / (e1 + e2), w1 = e2 / (e1 + e2);

    if (lane == 0) {
        int p0 = b * 2, p1 = b * 2 + 1;
        g_route[p0] = i1; g_route[p1] = i2;
        g_w[p0] = w0;     g_w[p1] = w1;
        int q0 = atomicAdd(&g_cnt[i1], 1); g_list[i1 * BATCH + q0] = p0;
        int q1 = atomicAdd(&g_cnt[i2], 1); g_list[i2 * BATCH + q1] = p1;
    }
    __syncthreads();
    if (threadIdx.x == 0) {
        __threadfence();
        int old = atomicAdd(&g_done, 1);
        if (old == gridDim.x - 1) {
            int t = 0;
            for (int e = 0; e < NEXP; e++) {
                int nt = (g_cnt[e] + 127) >> 7;
                for (int mm = 0; mm < nt; mm++) { g_tile_e[t] = e; g_tile_mt[t] = mm; t++; }
            }
            g_ntiles = t;
            g_work = 0;
            g_done = 0;
        }
    }
}

// ---------------- encode: tf32 mma.sync GEMM, hi/lo pre-split in smem ----------------
// block tile 128M x 128N, K-chunks CK=8 double-buffered (uint2 = (hi,lo) per value)
// 8 warps (4M x 2N), warp tile 32M x 64N = 2 m-tiles x 8 n-tiles of m16n8k8
#define CK    8
#define NCH   (DIM / CK)     // 96
#define SR2   10             // smem row stride in uint2 (80 B)
#define NBLK  (KD / 128)     // 12

__global__ void __launch_bounds__(256, 2) k_encode(const float* __restrict__ Wenc,
                                                   const float* __restrict__ benc) {
    __shared__ uint2 Xs[2][128 * SR2];
    __shared__ uint2 Ws[2][128 * SR2];
    __shared__ int   s_pair[128];
    __shared__ float s_bias[128];
    __shared__ int   s_w;

    int tid  = threadIdx.x;
    int wid  = tid >> 5;
    int lane = tid & 31;
    int g = lane >> 2, t = lane & 3;
    int warp_m = wid & 3;
    int warp_n = wid >> 2;
    int mbase = warp_m * 32;
    int nbase = warp_n * 64;
    int lrow = tid >> 1;         // loader row 0..127
    int lh4  = (tid & 1) * 4;    // loader k-offset 0 or 4
    int tot = g_ntiles * NBLK;

#pragma unroll 1
    while (true) {
        if (tid == 0) s_w = atomicAdd(&g_work, 1);
        __syncthreads();
        int w = s_w;
        if (w >= tot) break;
        int tile = w / NBLK;
        int nb   = w - tile * NBLK;
        int e  = g_tile_e[tile];
        int mt = g_tile_mt[tile];
        int cnt = g_cnt[e];
        int m0 = mt * 128;
        int n0 = nb * 128;

        if (tid < 128) {
            int m = m0 + tid;
            s_pair[tid] = (m < cnt) ? g_list[e * BATCH + m] : -1;
            s_bias[tid] = benc[(size_t)e * KD + n0 + tid];
        }
        __syncthreads();

        float acc[2][8][4];
#pragma unroll
        for (int i = 0; i < 2; i++)
#pragma unroll
            for (int j = 0; j < 8; j++)
#pragma unroll
                for (int q = 0; q < 4; q++) acc[i][j][q] = 0.f;

        int pairL = s_pair[lrow];
        int tokenL = (pairL >= 0 ? pairL : 0) >> 1;
        const float* xrow = g_X + (size_t)tokenL * DIM + lh4;
        const float* wrow = Wenc + (size_t)e * KD * DIM + (size_t)(n0 + lrow) * DIM + lh4;

        // chunk 0 -> buf 0 (convert once at store)
        {
            float4 xv = *(const float4*)(xrow);
            float4 wv = *(const float4*)(wrow);
            uint2* xd = &Xs[0][lrow * SR2 + lh4];
            uint2* wd = &Ws[0][lrow * SR2 + lh4];
            xd[0] = split_tf(xv.x); xd[1] = split_tf(xv.y);
            xd[2] = split_tf(xv.z); xd[3] = split_tf(xv.w);
            wd[0] = split_tf(wv.x); wd[1] = split_tf(wv.y);
            wd[2] = split_tf(wv.z); wd[3] = split_tf(wv.w);
        }
        __syncthreads();

#pragma unroll 1
        for (int c = 0; c < NCH; c++) {
            int buf = c & 1;
            float4 px, pw;
            if (c + 1 < NCH) {
                px = *(const float4*)(xrow + (c + 1) * CK);
                pw = *(const float4*)(wrow + (c + 1) * CK);
            }
            // A fragments (hi/lo) for 2 m-tiles
            uint32_t ahi[2][4], alo[2][4];
#pragma unroll
            for (int mi = 0; mi < 2; mi++) {
                int r0 = (mbase + mi * 16 + g) * SR2 + t;
                int r1 = (mbase + mi * 16 + g + 8) * SR2 + t;
                uint2 a0 = Xs[buf][r0];
                uint2 a1 = Xs[buf][r1];
                uint2 a2 = Xs[buf][r0 + 4];
                uint2 a3 = Xs[buf][r1 + 4];
                ahi[mi][0] = a0.x; alo[mi][0] = a0.y;
                ahi[mi][1] = a1.x; alo[mi][1] = a1.y;
                ahi[mi][2] = a2.x; alo[mi][2] = a2.y;
                ahi[mi][3] = a3.x; alo[mi][3] = a3.y;
            }
#pragma unroll
            for (int nt = 0; nt < 8; nt++) {
                int rb = (nbase + nt * 8 + g) * SR2 + t;
                uint2 b0 = Ws[buf][rb];
                uint2 b1 = Ws[buf][rb + 4];
                uint32_t bhi[2] = {b0.x, b1.x};
                uint32_t blo[2] = {b0.y, b1.y};
#pragma unroll
                for (int mi = 0; mi < 2; mi++) {
                    mma_tf32(acc[mi][nt], ahi[mi], bhi);
                    mma_tf32(acc[mi][nt], ahi[mi], blo);
                    mma_tf32(acc[mi][nt], alo[mi], bhi);
                }
            }
            if (c + 1 < NCH) {
                int nb2 = buf ^ 1;
                uint2* xd = &Xs[nb2][lrow * SR2 + lh4];
                uint2* wd = &Ws[nb2][lrow * SR2 + lh4];
                xd[0] = split_tf(px.x); xd[1] = split_tf(px.y);
                xd[2] = split_tf(px.z); xd[3] = split_tf(px.w);
                wd[0] = split_tf(pw.x); wd[1] = split_tf(pw.y);
                wd[2] = split_tf(pw.z); wd[3] = split_tf(pw.w);
                __syncthreads();
            }
        }

        // epilogue: bias + relu + gate-weight
#pragma unroll
        for (int mi = 0; mi < 2; mi++) {
#pragma unroll
            for (int half = 0; half < 2; half++) {
                int m = mbase + mi * 16 + g + half * 8;
                int pair = s_pair[m];
                if (pair < 0) continue;
                float wgt = g_w[pair];
                float* dst = g_F + (size_t)pair * KD + n0;
#pragma unroll
                for (int nt = 0; nt < 8; nt++) {
                    int col = nbase + nt * 8 + 2 * t;
                    float2 o;
                    o.x = fmaxf(acc[mi][nt][half * 2 + 0] + s_bias[col],     0.f) * wgt;
                    o.y = fmaxf(acc[mi][nt][half * 2 + 1] + s_bias[col + 1], 0.f) * wgt;
                    *(float2*)(dst + col) = o;
                }
            }
        }
        __syncthreads();
    }
}

// ---------------- decode: hist + 2-bit radix top-50 ----------------
__global__ void __launch_bounds__(192) k_decode(const float* __restrict__ b_dec,
                                                const float* __restrict__ Wdec,
                                                float* __restrict__ out) {
    int b = blockIdx.x;
    int tid = threadIdx.x;
    int lane = tid & 31;
    int wid = tid >> 5;

    __shared__ float    sf[KD];
    __shared__ int      hist[256];
    __shared__ int      cntS[36];
    __shared__ int      sel[56];
    __shared__ int      s_nsel, s_E, s_special;

    float4 bd = *(const float4*)(b_dec + tid * 4);
    u64 acc01, acc23;
    PACK2(acc01, bd.x, bd.y);
    PACK2(acc23, bd.z, bd.w);

    for (int slot = 0; slot < 2; slot++) {
        int pair = b * 2 + slot;
        int e = g_route[pair];
        const float* Fr = g_F + (size_t)pair * KD;

        for (int i = tid; i < 256; i += 192) hist[i] = 0;
        if (tid < 36) cntS[tid] = 0;
        unsigned rv[8];
#pragma unroll
        for (int j = 0; j < 8; j++) {
            float v = Fr[tid + 192 * j];
            sf[tid + 192 * j] = v;
            rv[j] = __float_as_uint(v);
        }
        __syncthreads();

#pragma unroll
        for (int j = 0; j < 8; j++)
            if (rv[j]) atomicAdd(&hist[rv[j] >> 23], 1);
        __syncthreads();

        if (wid == 0) {
            int base = 255 - 8 * lane;
            int c[8], cl = 0;
#pragma unroll
            for (int j = 0; j < 8; j++) { c[j] = hist[base - j]; cl += c[j]; }
            int incl = cl;
#pragma unroll
            for (int o = 1; o < 32; o <<= 1) {
                int tt = __shfl_up_sync(0xffffffffu, incl, o);
                if (lane >= o) incl += tt;
            }
            int pre = incl - cl;
            int total = __shfl_sync(0xffffffffu, incl, 31);
            if (total < KSEL) {
                if (lane == 0) s_special = 1;
            } else {
                bool owns = (pre < KSEL) && (incl >= KSEL);
                unsigned om = __ballot_sync(0xffffffffu, owns);
                int ol = __ffs(om) - 1;
                int Ev = 0;
                if (owns) {
                    int cum = pre;
#pragma unroll
                    for (int j = 0; j < 8; j++) {
                        if (cum + c[j] >= KSEL) { Ev = base - j; break; }
                        cum += c[j];
                    }
                }
                Ev = __shfl_sync(0xffffffffu, Ev, ol);
                if (lane == 0) { s_special = 0; s_E = Ev; }
            }
        }
        __syncthreads();

        unsigned thr;
        if (!s_special) {
            unsigned lo = (unsigned)s_E << 23;
#pragma unroll 1
            for (int it = 0; it < 11; it++) {
                int s = 21 - 2 * it;
                unsigned t1 = lo | (1u << s);
                unsigned t2 = lo | (2u << s);
                unsigned t3 = lo | (3u << s);
                int c1 = 0, c2 = 0, c3 = 0;
#pragma unroll
                for (int j = 0; j < 8; j++) {
                    c1 += (rv[j] >= t1);
                    c2 += (rv[j] >= t2);
                    c3 += (rv[j] >= t3);
                }
                c1 = __reduce_add_sync(0xffffffffu, c1);
                c2 = __reduce_add_sync(0xffffffffu, c2);
                c3 = __reduce_add_sync(0xffffffffu, c3);
                if (lane == 0) {
                    atomicAdd(&cntS[it * 3 + 0], c1);
                    atomicAdd(&cntS[it * 3 + 1], c2);
                    atomicAdd(&cntS[it * 3 + 2], c3);
                }
                __syncthreads();
                int C1 = cntS[it * 3 + 0], C2 = cntS[it * 3 + 1], C3 = cntS[it * 3 + 2];
                unsigned d = (C3 >= KSEL) ? 3u : (C2 >= KSEL) ? 2u : (C1 >= KSEL) ? 1u : 0u;
                lo |= d << s;
            }
            {
                unsigned tt = lo | 1u;
                int c = 0;
#pragma unroll
                for (int j = 0; j < 8; j++) c += (rv[j] >= tt);
                c = __reduce_add_sync(0xffffffffu, c);
                if (lane == 0) atomicAdd(&cntS[33], c);
                __syncthreads();
                if (cntS[33] >= KSEL) lo |= 1u;
            }
            thr = lo;
        } else {
            thr = 1u;
        }

        if (tid < 32) {
            int ns = 0;
            for (int base = 0; base < KD; base += 32) {
                unsigned bits = __float_as_uint(sf[base + tid]);
                bool p = (bits >= thr) && (bits != 0u);
                unsigned msk = __ballot_sync(0xffffffffu, p);
                int pos = ns + __popc(msk & ((1u << tid) - 1u));
                if (p && pos < KSEL) sel[pos] = base + tid;
                ns += __popc(msk);
            }
            if (tid == 0) s_nsel = (ns < KSEL ? ns : KSEL);
        }
        __syncthreads();
        int nsel = s_nsel;

        const float* Wd = Wdec + (size_t)e * KD * DIM + tid * 4;
        int i = 0;
        for (; i + 4 <= nsel; i += 4) {
            int k0 = sel[i], k1 = sel[i + 1], k2 = sel[i + 2], k3 = sel[i + 3];
            float f0 = sf[k0], f1 = sf[k1], f2 = sf[k2], f3 = sf[k3];
            float4 w0 = *(const float4*)(Wd + (size_t)k0 * DIM);
            float4 w1 = *(const float4*)(Wd + (size_t)k1 * DIM);
            float4 w2 = *(const float4*)(Wd + (size_t)k2 * DIM);
            float4 w3 = *(const float4*)(Wd + (size_t)k3 * DIM);
            u64 fp, t;
            PACK2(fp, f0, f0);
            PACK2(t, w0.x, w0.y); FMA2(acc01, fp, t);
            PACK2(t, w0.z, w0.w); FMA2(acc23, fp, t);
            PACK2(fp, f1, f1);
            PACK2(t, w1.x, w1.y); FMA2(acc01, fp, t);
            PACK2(t, w1.z, w1.w); FMA2(acc23, fp, t);
            PACK2(fp, f2, f2);
            PACK2(t, w2.x, w2.y); FMA2(acc01, fp, t);
            PACK2(t, w2.z, w2.w); FMA2(acc23, fp, t);
            PACK2(fp, f3, f3);
            PACK2(t, w3.x, w3.y); FMA2(acc01, fp, t);
            PACK2(t, w3.z, w3.w); FMA2(acc23, fp, t);
        }
        for (; i < nsel; i++) {
            int k0 = sel[i];
            float f0 = sf[k0];
            float4 w0 = *(const float4*)(Wd + (size_t)k0 * DIM);
            u64 fp, t;
            PACK2(fp, f0, f0);
            PACK2(t, w0.x, w0.y); FMA2(acc01, fp, t);
            PACK2(t, w0.z, w0.w); FMA2(acc23, fp, t);
        }
        __syncthreads();
    }

    float4 r;
    UNPACK2(r.x, r.y, acc01);
    UNPACK2(r.z, r.w, acc23);
    *(float4*)(out + (size_t)b * DIM + tid * 4) = r;
}

// ---------------- launch ----------------
extern "C" void kernel_launch(void* const* d_in, const int* in_sizes, int n_in,
                              void* d_out, int out_size) {
    const float* x      = (const float*)d_in[0];
    const float* Wg     = (const float*)d_in[1];
    const float* bg     = (const float*)d_in[2];
    const float* b_gate = (const float*)d_in[3];
    const float* b_dec  = (const float*)d_in[4];
    const float* Wenc   = (const float*)d_in[5];
    const float* benc   = (const float*)d_in[6];
    const float* Wdec   = (const float*)d_in[7];
    float* out = (float*)d_out;

    k_init<<<1, 32>>>();
    k_gate<<<BATCH / 4, 128>>>(x, Wg, bg, b_gate, b_dec);
    k_encode<<<296, 256>>>(Wenc, benc);
    k_decode<<<BATCH, 192>>>(b_dec, Wdec, out);
}